// round 7
// baseline (speedup 1.0000x reference)
#include <cuda_runtime.h>
#include <math.h>
#include <stdint.h>

// ---------------- problem dims ----------------
#define TT 128
#define NN 1024
#define HH 512
#define II 64
#define G3 1536
#define NSTRIP 16
#define NKSTG 16
#define NTH 512

// ---------------- device scratch ----------------
// weights: [strip][kstage][96 rows][32 k]; rows grouped as (hcolgrp*24 + gate*8 + e),
// k XOR-swizzled by 8*(row&3)
__device__ float g_Whh2[NSTRIP * NKSTG * 96 * 32];
__device__ float g_Wih_t[G3 * II];
__device__ float g_hA2[2][NKSTG * NN * 32];       // tf32 h ping-pong
__device__ float g_Gi[(size_t)TT * NSTRIP * NN * 96]; // [t][strip][n][96 cr-order]
__device__ unsigned g_sync[8];                    // rowblock barriers

// ---------------- helpers ----------------
__device__ __forceinline__ uint32_t f2tf32(float f) {
    uint32_t r;
    asm("cvt.rna.tf32.f32 %0, %1;" : "=r"(r) : "f"(f));
    return r;
}
__device__ __forceinline__ uint32_t smem_u32(const void* p) {
    uint32_t a;
    asm("{ .reg .u64 t; cvta.to.shared.u64 t, %1; cvt.u32.u64 %0, t; }" : "=r"(a) : "l"(p));
    return a;
}
__device__ __forceinline__ float sigf(float x) { return 1.0f / (1.0f + __expf(-x)); }

#define MBARRIER_INIT(addr, cnt) \
    asm volatile("mbarrier.init.shared.b64 [%0], %1;" :: "r"(addr), "r"(cnt) : "memory")
#define MBARRIER_EXPECT_TX(addr, tx) \
    asm volatile("mbarrier.arrive.expect_tx.shared.b64 _, [%0], %1;" \
                 :: "r"(addr), "r"(tx) : "memory")
#define MBARRIER_WAIT_PARITY(mbar_addr, phase_parity) do {                                 \
    uint32_t _mbar = (uint32_t)(mbar_addr);                                                \
    uint32_t _parity = (uint32_t)(phase_parity);                                           \
    uint32_t _done;                                                                        \
    asm volatile(                                                                          \
        "{\n\t.reg .pred p;\n\t"                                                           \
        "mbarrier.try_wait.parity.acquire.cta.shared::cta.b64 p, [%1], %2;\n\t"            \
        "selp.b32 %0, 1, 0, p;\n\t}"                                                       \
        : "=r"(_done) : "r"(_mbar), "r"(_parity) : "memory");                              \
    if (!_done) {                                                                          \
        asm volatile(                                                                      \
            "{\n\t.reg .pred P1;\n\t"                                                      \
            "WAIT_LOOP_%=:\n\t"                                                            \
            "mbarrier.try_wait.parity.acquire.cta.shared::cta.b64 P1, [%0], %1, 0x989680;\n\t" \
            "@P1 bra.uni WAIT_DONE_%=;\n\t"                                                \
            "bra.uni WAIT_LOOP_%=;\n\t"                                                    \
            "WAIT_DONE_%=:\n\t}"                                                           \
            :: "r"(_mbar), "r"(_parity) : "memory");                                       \
    }                                                                                      \
} while (0)

#define BULK_G2S(dst_smem, src_gmem, bytes, mbar) \
    asm volatile("cp.async.bulk.shared::cluster.global.mbarrier::complete_tx::bytes " \
                 "[%0], [%1], %2, [%3];" \
                 :: "r"(dst_smem), "l"(src_gmem), "r"(bytes), "r"(mbar) : "memory")

__device__ __forceinline__ void mma_tf32(float (&c)[4], const uint32_t (&a)[4],
                                         const uint32_t (&b)[2]) {
    asm volatile(
        "mma.sync.aligned.m16n8k8.row.col.f32.tf32.tf32.f32 "
        "{%0,%1,%2,%3}, {%4,%5,%6,%7}, {%8,%9}, {%0,%1,%2,%3};"
        : "+f"(c[0]), "+f"(c[1]), "+f"(c[2]), "+f"(c[3])
        : "r"(a[0]), "r"(a[1]), "r"(a[2]), "r"(a[3]), "r"(b[0]), "r"(b[1]));
}

// ================= prep =================
__global__ void prep_kernel(const float* __restrict__ W_hh,
                            const float* __restrict__ W_ih,
                            const float* __restrict__ hxs) {
    int idx = blockIdx.x * blockDim.x + threadIdx.x;
    if (idx < 8) g_sync[idx] = 0;
    if (idx < G3 * HH) {                         // W_hh[r][k]
        int r = idx >> 9, k = idx & 511;
        int gg = r >> 9, u = r & 511, s = u >> 5, c = u & 31;
        int cr = (c >> 3) * 24 + gg * 8 + (c & 7);
        int kst = k >> 5, kk = k & 31;
        g_Whh2[((s * NKSTG + kst) * 96 + cr) * 32 + (kk ^ (8 * (cr & 3)))] =
            __uint_as_float(f2tf32(W_hh[idx]));
    }
    if (idx < G3 * II) g_Wih_t[idx] = __uint_as_float(f2tf32(W_ih[idx]));
    if (idx < NN * HH) {
        int n = idx >> 9, k = idx & 511;
        int kst = k >> 5, kk = k & 31;
        g_hA2[0][(kst * NN + n) * 32 + (kk ^ (8 * (n & 3)))] =
            __uint_as_float(f2tf32(hxs[idx]));
    }
}

// ================= Gi precompute =================
#define GI_SST 68
__global__ __launch_bounds__(256, 1)
void gi_kernel(const float* __restrict__ X) {
    extern __shared__ float sm[];
    float* Xs = sm;
    float* Ws = sm + 128 * GI_SST;
    const int tid = threadIdx.x;
    const int rb = blockIdx.y * 128;
    const int cb = blockIdx.x * 128;

    #pragma unroll
    for (int it = 0; it < 8; it++) {
        int id = it * 256 + tid;
        int row = id >> 4, c4 = (id & 15) * 4;
        float4 v = *reinterpret_cast<const float4*>(X + (size_t)(rb + row) * II + c4);
        uint4 o = make_uint4(f2tf32(v.x), f2tf32(v.y), f2tf32(v.z), f2tf32(v.w));
        *reinterpret_cast<uint4*>(Xs + row * GI_SST + c4) = o;
        float4 w = *reinterpret_cast<const float4*>(g_Wih_t + (size_t)(cb + row) * II + c4);
        *reinterpret_cast<float4*>(Ws + row * GI_SST + c4) = w;
    }
    __syncthreads();

    const int w = tid >> 5, lane = tid & 31, g = lane >> 2, t = lane & 3;
    const int wr = w & 3, wc = w >> 2;
    float acc[2][8][4];
    #pragma unroll
    for (int sl = 0; sl < 2; sl++)
        #pragma unroll
        for (int j = 0; j < 8; j++)
            #pragma unroll
            for (int q = 0; q < 4; q++) acc[sl][j][q] = 0.0f;

    #pragma unroll
    for (int k8 = 0; k8 < 8; k8++) {
        const int kb = k8 * 8;
        uint32_t a[2][4], b[8][2];
        #pragma unroll
        for (int sl = 0; sl < 2; sl++) {
            int m0 = wr * 32 + sl * 16;
            a[sl][0] = __float_as_uint(Xs[(m0 + g) * GI_SST + kb + t]);
            a[sl][1] = __float_as_uint(Xs[(m0 + 8 + g) * GI_SST + kb + t]);
            a[sl][2] = __float_as_uint(Xs[(m0 + g) * GI_SST + kb + t + 4]);
            a[sl][3] = __float_as_uint(Xs[(m0 + 8 + g) * GI_SST + kb + t + 4]);
        }
        #pragma unroll
        for (int j = 0; j < 8; j++) {
            int n0 = wc * 64 + j * 8;
            b[j][0] = __float_as_uint(Ws[(n0 + g) * GI_SST + kb + t]);
            b[j][1] = __float_as_uint(Ws[(n0 + g) * GI_SST + kb + t + 4]);
        }
        #pragma unroll
        for (int sl = 0; sl < 2; sl++)
            #pragma unroll
            for (int j = 0; j < 8; j++) mma_tf32(acc[sl][j], a[sl], b[j]);
    }

    #pragma unroll
    for (int sl = 0; sl < 2; sl++) {
        #pragma unroll
        for (int j = 0; j < 8; j++) {
            int row = rb + wr * 32 + sl * 16 + g;
            int col = cb + wc * 64 + j * 8 + 2 * t;
            int tt = row >> 10, n = row & 1023;
            int gg = col >> 9, hcol = col & 511, s = hcol >> 5, cl = hcol & 31;
            int cr = (cl >> 3) * 24 + gg * 8 + (cl & 7);
            size_t base0 = (((size_t)tt * NSTRIP + s) * NN + n) * 96 + cr;
            *reinterpret_cast<float2*>(g_Gi + base0) =
                make_float2(acc[sl][j][0], acc[sl][j][1]);
            size_t base1 = (((size_t)tt * NSTRIP + s) * NN + (n + 8)) * 96 + cr;
            *reinterpret_cast<float2*>(g_Gi + base1) =
                make_float2(acc[sl][j][2], acc[sl][j][3]);
        }
    }
}

// ================= persistent GRU kernel =================
#define SW_B   196608                 // resident weights: 16 stages x 12288 B
#define A_OFF  196608                 // 2 x 16384 A double buffer
#define SB_OFF 229376                 // bias cache: 4 x 32 floats = 512 B
#define MB_OFF 229888                 // mb0, mb1, mbW
#define SMEM_STEP 229920

__global__ __launch_bounds__(NTH, 1)
void gru_persist(const float* __restrict__ hxs,
                 const float* __restrict__ masks,
                 const float* __restrict__ b_ih,
                 const float* __restrict__ b_hh,
                 float* __restrict__ out,
                 int has_tail) {
    extern __shared__ char smem[];
    const uint32_t sbase = smem_u32(smem);
    const int tid = threadIdx.x;
    const int strip = blockIdx.x;       // 0..15
    const int rbIdx = blockIdx.y;       // 0..7
    const int rb = rbIdx * 128;

    const uint32_t mb0 = sbase + MB_OFF;
    const uint32_t mb1 = mb0 + 8;
    const uint32_t mbW = mb0 + 16;

    const int w = tid >> 5, lane = tid & 31, g = lane >> 2, t2 = (lane & 3) * 2;
    const int wr = w & 7, wc = w >> 3;
    const int r0l = wr * 16 + g;
    const int sw0 = 8 * (g & 3);

    if (tid == 0) {
        MBARRIER_INIT(mb0, 1);
        MBARRIER_INIT(mb1, 1);
        MBARRIER_INIT(mbW, 1);
    }
    float* sbr  = (float*)(smem + SB_OFF);
    float* sbz  = sbr + 32;
    float* sbni = sbr + 64;
    float* sbnh = sbr + 96;
    if (tid < 32) {
        int gc = strip * 32 + tid;
        sbr[tid]  = b_ih[gc] + b_hh[gc];
        sbz[tid]  = b_ih[512 + gc] + b_hh[512 + gc];
        sbni[tid] = b_ih[1024 + gc];
        sbnh[tid] = b_hh[1024 + gc];
    }
    __syncthreads();

    const float* Wstrip = g_Whh2 + (size_t)strip * NKSTG * 96 * 32;
    if (tid == 0) {
        MBARRIER_EXPECT_TX(mbW, SW_B);
        #pragma unroll
        for (int c4 = 0; c4 < 4; c4++)
            BULK_G2S(sbase + c4 * 49152, Wstrip + c4 * 12288, 49152, mbW);
        // prefetch A stages 0,1 of t=0 (hA parity 0)
        MBARRIER_EXPECT_TX(mb0, 16384);
        BULK_G2S(sbase + A_OFF, &g_hA2[0][(size_t)rb * 32], 16384, mb0);
        MBARRIER_EXPECT_TX(mb1, 16384);
        BULK_G2S(sbase + A_OFF + 16384, &g_hA2[0][((size_t)NN + rb) * 32], 16384, mb1);
    }
    MBARRIER_WAIT_PARITY(mbW, 0);

    const int R0 = rb + r0l;
    const int R1 = R0 + 8;

    for (int t = 0; t < TT; t++) {
        const int par = t & 1;
        const float* hA  = g_hA2[par];
        float*       hAn = g_hA2[par ^ 1];
        const float* hp_base = (t == 0) ? hxs : out + (size_t)(t - 1) * NN * HH;
        const float* Gi_t = g_Gi + ((size_t)t * NSTRIP + strip) * NN * 96;
        const float* mt = masks + (size_t)t * NN;

        // ---- epilogue operand prefetch into registers (hides DRAM latency) ----
        const float m0v = mt[R0];
        const float m1v = mt[R1];
        float2 giv[2][3][2], hpv[2][2];
        #pragma unroll
        for (int g3 = 0; g3 < 2; g3++) {
            const int hgrp = wc * 2 + g3;
            const int crb = hgrp * 24 + t2;
            const int hc = hgrp * 8 + t2;
            #pragma unroll
            for (int gate = 0; gate < 3; gate++) {
                giv[g3][gate][0] =
                    *reinterpret_cast<const float2*>(&Gi_t[(size_t)R0 * 96 + crb + gate * 8]);
                giv[g3][gate][1] =
                    *reinterpret_cast<const float2*>(&Gi_t[(size_t)R1 * 96 + crb + gate * 8]);
            }
            hpv[g3][0] = *reinterpret_cast<const float2*>(
                &hp_base[(size_t)R0 * HH + strip * 32 + hc]);
            hpv[g3][1] = *reinterpret_cast<const float2*>(
                &hp_base[(size_t)R1 * HH + strip * 32 + hc]);
        }

        // ---- mainloop: 16 A-stages, weights resident ----
        float acc[6][4];
        #pragma unroll
        for (int j = 0; j < 6; j++)
            #pragma unroll
            for (int q = 0; q < 4; q++) acc[j][q] = 0.0f;

        for (int s = 0; s < NKSTG; s++) {
            MBARRIER_WAIT_PARITY(mb0 + 8 * (s & 1), (s >> 1) & 1);
            const float* As = (const float*)(smem + A_OFF + (s & 1) * 16384);
            const float* Bs = (const float*)(smem + s * 12288);
            #pragma unroll
            for (int k8 = 0; k8 < 4; k8++) {
                const int koff = (k8 * 8 + t2) ^ sw0;
                float2 a0 = *reinterpret_cast<const float2*>(&As[r0l * 32 + koff]);
                float2 a1 = *reinterpret_cast<const float2*>(&As[(r0l + 8) * 32 + koff]);
                uint32_t a[4] = {__float_as_uint(a0.x), __float_as_uint(a1.x),
                                 __float_as_uint(a0.y), __float_as_uint(a1.y)};
                #pragma unroll
                for (int j = 0; j < 6; j++) {
                    int cr = wc * 48 + j * 8 + g;
                    float2 bv = *reinterpret_cast<const float2*>(&Bs[cr * 32 + koff]);
                    uint32_t b[2] = {__float_as_uint(bv.x), __float_as_uint(bv.y)};
                    mma_tf32(acc[j], a, b);
                }
            }
            __syncthreads();
            if (tid == 0 && s + 2 < NKSTG) {
                MBARRIER_EXPECT_TX(mb0 + 8 * (s & 1), 16384);
                BULK_G2S(sbase + A_OFF + (s & 1) * 16384,
                         hA + ((size_t)(s + 2) * NN + rb) * 32, 16384, mb0 + 8 * (s & 1));
            }
        }

        // ---- epilogue: gates straight from fragments ----
        float* outT = out + (size_t)t * NN * HH;
        #pragma unroll
        for (int g3 = 0; g3 < 2; g3++) {
            const int jb = g3 * 3;
            const int hc = (wc * 2 + g3) * 8 + t2;
            const int gcol = strip * 32 + hc;
            #pragma unroll
            for (int rs = 0; rs < 2; rs++) {
                const int row = rs ? R1 : R0;
                const float m = rs ? m1v : m0v;
                const float sr0 = acc[jb + 0][rs * 2], sr1 = acc[jb + 0][rs * 2 + 1];
                const float sz0 = acc[jb + 1][rs * 2], sz1 = acc[jb + 1][rs * 2 + 1];
                const float sn0 = acc[jb + 2][rs * 2], sn1 = acc[jb + 2][rs * 2 + 1];
                const float2 gr = giv[g3][0][rs];
                const float2 gz = giv[g3][1][rs];
                const float2 gn = giv[g3][2][rs];
                const float2 hpq = hpv[g3][rs];

                float rv0 = sigf(fmaf(m, sr0 + gr.x, sbr[hc]));
                float rv1 = sigf(fmaf(m, sr1 + gr.y, sbr[hc + 1]));
                float zv0 = sigf(fmaf(m, sz0 + gz.x, sbz[hc]));
                float zv1 = sigf(fmaf(m, sz1 + gz.y, sbz[hc + 1]));
                float nv0 = tanhf(fmaf(m, gn.x, sbni[hc]) + rv0 * fmaf(m, sn0, sbnh[hc]));
                float nv1 = tanhf(fmaf(m, gn.y, sbni[hc + 1]) +
                                  rv1 * fmaf(m, sn1, sbnh[hc + 1]));
                float h0 = fmaf(zv0, fmaf(m, hpq.x, -nv0), nv0);
                float h1 = fmaf(zv1, fmaf(m, hpq.y, -nv1), nv1);

                *reinterpret_cast<float2*>(&outT[(size_t)row * HH + gcol]) =
                    make_float2(h0, h1);
                if (has_tail && t == TT - 1)
                    *reinterpret_cast<float2*>(
                        &out[(size_t)TT * NN * HH + (size_t)row * HH + gcol]) =
                        make_float2(h0, h1);
                uint2 oc = make_uint2(f2tf32(h0), f2tf32(h1));
                *reinterpret_cast<uint2*>(
                    &hAn[((size_t)strip * NN + row) * 32 + (hc ^ (8 * (row & 3)))]) = oc;
            }
        }

        // ---- rowblock barrier + next-step A prefetch ----
        if (t + 1 < TT) {
            __threadfence();
            __syncthreads();
            if (tid == 0) {
                asm volatile("fence.proxy.async;" ::: "memory");
                atomicAdd(&g_sync[rbIdx], 1u);
                const unsigned target = 16u * (unsigned)(t + 1);
                unsigned v;
                do {
                    asm volatile("ld.global.acquire.gpu.u32 %0, [%1];"
                                 : "=r"(v) : "l"(&g_sync[rbIdx]) : "memory");
                } while (v < target);
                asm volatile("fence.proxy.async;" ::: "memory");
                MBARRIER_EXPECT_TX(mb0, 16384);
                BULK_G2S(sbase + A_OFF, hAn + (size_t)rb * 32, 16384, mb0);
                MBARRIER_EXPECT_TX(mb1, 16384);
                BULK_G2S(sbase + A_OFF + 16384, hAn + ((size_t)NN + rb) * 32, 16384, mb1);
            }
            __syncthreads();
        }
    }
}

// ---------------- host ----------------
extern "C" void kernel_launch(void* const* d_in, const int* in_sizes, int n_in,
                              void* d_out, int out_size) {
    const float* hxs   = (const float*)d_in[0];
    const float* masks = (const float*)d_in[2];
    const float* pact  = (const float*)d_in[3];
    const float* W_ih  = (const float*)d_in[4];
    const float* W_hh  = (const float*)d_in[5];
    const float* b_ih  = (const float*)d_in[6];
    const float* b_hh  = (const float*)d_in[7];
    float* out = (float*)d_out;

    static bool attr_set = false;
    if (!attr_set) {
        cudaFuncSetAttribute(gi_kernel, cudaFuncAttributeMaxDynamicSharedMemorySize,
                             2 * 128 * GI_SST * 4);
        cudaFuncSetAttribute(gru_persist, cudaFuncAttributeMaxDynamicSharedMemorySize,
                             SMEM_STEP);
        attr_set = true;
    }

    // 1) prep (also resets rowblock barriers)
    prep_kernel<<<(G3 * HH + 255) / 256, 256>>>(W_hh, W_ih, hxs);

    // 2) Gi precompute
    {
        dim3 grid(G3 / 128, (TT * NN) / 128);
        gi_kernel<<<grid, 256, 2 * 128 * GI_SST * 4>>>(pact);
    }

    // 3) persistent kernel: all 128 steps
    const size_t stepElems = (size_t)NN * HH;
    const int has_tail =
        ((size_t)out_size >= (size_t)TT * stepElems + stepElems) ? 1 : 0;
    dim3 grid(NSTRIP, NN / 128);                 // (16, 8) = 128 CTAs, 1/SM
    gru_persist<<<grid, NTH, SMEM_STEP>>>(hxs, masks, b_ih, b_hh, out, has_tail);
}